// round 9
// baseline (speedup 1.0000x reference)
#include <cuda_runtime.h>
#include <cuda_fp16.h>

#define N_USERS 100000
#define N_ITEMS 200000
#define N_NODES (N_USERS + N_ITEMS)
#define NNZ     9600000
#define DIM     64
#define TOTAL   ((size_t)N_NODES * DIM)
#define TOTAL4  (TOTAL / 4)
#define CAP     128                     // slots/row; mean degree 32, ~17 sigma

// Scratch (__device__ globals, alloc-free rule).
// h0 = fp16(e0), h1 = e1, h2 = e2. Final combine reads fp32 inputs directly.
// bucket has +8 pad entries so unconditional next-chunk prefetch is in-bounds.
__device__ __align__(16) __half g_h0[TOTAL];
__device__ __align__(16) __half g_h1[TOTAL];
__device__ __align__(16) __half g_h2[TOTAL];
__device__ __align__(16) int2   g_bucket[(size_t)N_NODES * CAP + 8];
__device__ int g_cnt[N_NODES];

// ---------------------------------------------------------------------------
// init: g_h0 = fp16(concat(user,item)); g_cnt = 0.
// ---------------------------------------------------------------------------
__global__ __launch_bounds__(256) void init_kernel(
    const float* __restrict__ user_emb,
    const float* __restrict__ item_emb)
{
    size_t i = (size_t)blockIdx.x * blockDim.x + threadIdx.x;
    if (i < N_NODES) g_cnt[i] = 0;
    if (i >= TOTAL4) return;
    const size_t ub = (size_t)N_USERS * DIM / 4;
    float4 v = (i < ub) ? ((const float4*)user_emb)[i]
                        : ((const float4*)item_emb)[i - ub];
    uint2 h;
    __half2 h01 = __floats2half2_rn(v.x, v.y);
    __half2 h23 = __floats2half2_rn(v.z, v.w);
    h.x = *(unsigned*)&h01;
    h.y = *(unsigned*)&h23;
    ((uint2*)g_h0)[i] = h;
}

// ---------------------------------------------------------------------------
// Single-pass bucketing, 4 edges/thread via int4 loads (NNZ % 4 == 0).
// ---------------------------------------------------------------------------
__global__ __launch_bounds__(256) void bucket_kernel(
    const int*   __restrict__ rows,
    const int*   __restrict__ cols,
    const float* __restrict__ vals)
{
    int t = blockIdx.x * blockDim.x + threadIdx.x;
    int e = t * 4;
    if (e >= NNZ) return;
    int4 r4 = __ldcs((const int4*)(rows + e));
    int4 c4 = __ldcs((const int4*)(cols + e));
    int4 v4 = __ldcs((const int4*)(vals + e));
    int rr[4] = {r4.x, r4.y, r4.z, r4.w};
    int cc[4] = {c4.x, c4.y, c4.z, c4.w};
    int vv[4] = {v4.x, v4.y, v4.z, v4.w};
    #pragma unroll
    for (int k = 0; k < 4; k++) {
        int pos = atomicAdd(&g_cnt[rr[k]], 1);
        if (pos < CAP)
            g_bucket[(size_t)rr[k] * CAP + pos] = make_int2(cc[k], vv[k]);
    }
}

// ---------------------------------------------------------------------------
// Warp-per-row segment sum. 4 edges/iteration, with the NEXT chunk's meta
// prefetched before the current chunk's gathers (software pipeline) so the
// meta L2 latency hides behind the gathers. Lane owns 2 dims.
// ---------------------------------------------------------------------------
__device__ __forceinline__ void edge2_fma(
    const __half* __restrict__ src, int lane, int4 m, float2& sum)
{
    __half2 xa = __ldg((const __half2*)(src + (size_t)m.x * DIM) + lane);
    __half2 xb = __ldg((const __half2*)(src + (size_t)m.z * DIM) + lane);
    float va = __int_as_float(m.y);
    float vb = __int_as_float(m.w);
    float2 fa = __half22float2(xa);
    float2 fb = __half22float2(xb);
    sum.x = fmaf(fa.x, va, sum.x); sum.y = fmaf(fa.y, va, sum.y);
    sum.x = fmaf(fb.x, vb, sum.x); sum.y = fmaf(fb.y, vb, sum.y);
}

__device__ __forceinline__ float2 row_segsum(
    const __half* __restrict__ src, int row, int lane)
{
    int cnt = __ldg(&g_cnt[row]);
    if (cnt > CAP) cnt = CAP;
    const int2* ep = g_bucket + (size_t)row * CAP;

    float2 sum = make_float2(0.f, 0.f);
    int i = 0;
    if (cnt >= 4) {
        int4 ma = __ldg((const int4*)(ep));          // chunk 0 meta
        int4 mb = __ldg((const int4*)(ep + 2));
        for (; i + 3 < cnt; i += 4) {
            // prefetch next chunk (unconditional; pad keeps it in-bounds)
            int4 na = __ldg((const int4*)(ep + i + 4));
            int4 nb = __ldg((const int4*)(ep + i + 6));
            edge2_fma(src, lane, ma, sum);
            edge2_fma(src, lane, mb, sum);
            ma = na; mb = nb;
        }
    }
    for (; i < cnt; i++) {                           // tail (<=3)
        int2 ev = __ldg(ep + i);
        float v = __int_as_float(ev.y);
        __half2 x = __ldg((const __half2*)(src + (size_t)ev.x * DIM) + lane);
        float2 f = __half22float2(x);
        sum.x = fmaf(f.x, v, sum.x);
        sum.y = fmaf(f.y, v, sum.y);
    }
    return sum;
}

__global__ __launch_bounds__(256) void spmm_kernel(
    const __half* __restrict__ src,
    __half*       __restrict__ dst)
{
    int warp = (blockIdx.x * blockDim.x + threadIdx.x) >> 5;
    int lane = threadIdx.x & 31;
    if (warp >= N_NODES) return;
    float2 sum = row_segsum(src, warp, lane);
    ((__half2*)dst)[(size_t)warp * (DIM / 2) + lane] =
        __floats2half2_rn(sum.x, sum.y);
}

// Layer 3 + final combine: out = (e0_f32 + e1 + e2 + sum3) * 0.25
__global__ __launch_bounds__(256) void spmm_final_kernel(
    const __half* __restrict__ src,        // h2 (e2): gather source
    const float*  __restrict__ user_emb,
    const float*  __restrict__ item_emb,
    float*        __restrict__ out)
{
    int warp = (blockIdx.x * blockDim.x + threadIdx.x) >> 5;
    int lane = threadIdx.x & 31;
    if (warp >= N_NODES) return;
    float2 sum = row_segsum(src, warp, lane);

    size_t o = (size_t)warp * (DIM / 2) + lane;
    float2 e1 = __half22float2(__ldg((const __half2*)g_h1 + o));
    float2 e2 = __half22float2(__ldg((const __half2*)g_h2 + o));
    const float* inp = (warp < N_USERS)
        ? user_emb + (size_t)warp * DIM
        : item_emb + (size_t)(warp - N_USERS) * DIM;
    float2 e0 = __ldg((const float2*)inp + lane);

    float2 r;
    r.x = (e0.x + e1.x + e2.x + sum.x) * 0.25f;
    r.y = (e0.y + e1.y + e2.y + sum.y) * 0.25f;
    ((float2*)out)[o] = r;
}

extern "C" void kernel_launch(void* const* d_in, const int* in_sizes, int n_in,
                              void* d_out, int out_size)
{
    const int*   rows     = (const int*)  d_in[0];
    const int*   cols     = (const int*)  d_in[1];
    const float* vals     = (const float*)d_in[2];
    const float* user_emb = (const float*)d_in[3];
    const float* item_emb = (const float*)d_in[4];
    float*       out      = (float*)d_out;

    __half *h0, *h1, *h2;
    cudaGetSymbolAddress((void**)&h0, g_h0);
    cudaGetSymbolAddress((void**)&h1, g_h1);
    cudaGetSymbolAddress((void**)&h2, g_h2);

    const int thr = 256;
    const int bucket_blocks = (NNZ / 4 + thr - 1) / thr;
    const int vec_blocks  = (int)((TOTAL4 + thr - 1) / thr);
    const int spmm_blocks = (int)(((long long)N_NODES * 32 + thr - 1) / thr);

    init_kernel<<<vec_blocks, thr>>>(user_emb, item_emb);
    bucket_kernel<<<bucket_blocks, thr>>>(rows, cols, vals);

    spmm_kernel<<<spmm_blocks, thr>>>(h0, h1);              // e1 = A e0
    spmm_kernel<<<spmm_blocks, thr>>>(h1, h2);              // e2 = A e1
    spmm_final_kernel<<<spmm_blocks, thr>>>(h2, user_emb, item_emb, out);
}

// round 10
// speedup vs baseline: 1.0902x; 1.0902x over previous
#include <cuda_runtime.h>
#include <cuda_fp16.h>

#define N_USERS 100000
#define N_ITEMS 200000
#define N_NODES (N_USERS + N_ITEMS)
#define NNZ     9600000
#define DIM     64
#define TOTAL   ((size_t)N_NODES * DIM)
#define TOTAL4  (TOTAL / 4)
#define CAP     128                     // slots/row; mean degree 32, ~17 sigma

// Scratch (__device__ globals, alloc-free rule).
// h0 = fp16(e0), h1 = e1, h2 = e2. Final combine reads fp32 inputs directly.
__device__ __align__(16) __half g_h0[TOTAL];
__device__ __align__(16) __half g_h1[TOTAL];
__device__ __align__(16) __half g_h2[TOTAL];
__device__ __align__(16) int2   g_bucket[(size_t)N_NODES * CAP];
__device__ int g_cnt[N_NODES];

// ---------------------------------------------------------------------------
// init: g_h0 = fp16(concat(user,item)); g_cnt = 0.
// ---------------------------------------------------------------------------
__global__ __launch_bounds__(256) void init_kernel(
    const float* __restrict__ user_emb,
    const float* __restrict__ item_emb)
{
    size_t i = (size_t)blockIdx.x * blockDim.x + threadIdx.x;
    if (i < N_NODES) g_cnt[i] = 0;
    if (i >= TOTAL4) return;
    const size_t ub = (size_t)N_USERS * DIM / 4;
    float4 v = (i < ub) ? ((const float4*)user_emb)[i]
                        : ((const float4*)item_emb)[i - ub];
    uint2 h;
    __half2 h01 = __floats2half2_rn(v.x, v.y);
    __half2 h23 = __floats2half2_rn(v.z, v.w);
    h.x = *(unsigned*)&h01;
    h.y = *(unsigned*)&h23;
    ((uint2*)g_h0)[i] = h;
}

// ---------------------------------------------------------------------------
// Single-pass bucketing, 4 edges/thread via int4 loads (NNZ % 4 == 0).
// (Kept from R9 — it saved ~60us.)
// ---------------------------------------------------------------------------
__global__ __launch_bounds__(256) void bucket_kernel(
    const int*   __restrict__ rows,
    const int*   __restrict__ cols,
    const float* __restrict__ vals)
{
    int t = blockIdx.x * blockDim.x + threadIdx.x;
    int e = t * 4;
    if (e >= NNZ) return;
    int4 r4 = __ldcs((const int4*)(rows + e));
    int4 c4 = __ldcs((const int4*)(cols + e));
    int4 v4 = __ldcs((const int4*)(vals + e));
    int rr[4] = {r4.x, r4.y, r4.z, r4.w};
    int cc[4] = {c4.x, c4.y, c4.z, c4.w};
    int vv[4] = {v4.x, v4.y, v4.z, v4.w};
    #pragma unroll
    for (int k = 0; k < 4; k++) {
        int pos = atomicAdd(&g_cnt[rr[k]], 1);
        if (pos < CAP)
            g_bucket[(size_t)rr[k] * CAP + pos] = make_int2(cc[k], vv[k]);
    }
}

// ---------------------------------------------------------------------------
// Warp-per-row segment sum. Flat 8-edge unroll: 4 independent int4 meta
// loads + 8 independent gathers per iteration (no cross-iteration registers,
// unlike the R9 prefetch pipeline that tanked occupancy). Lane owns 2 dims.
// ---------------------------------------------------------------------------
__device__ __forceinline__ void edge2_fma(
    const __half* __restrict__ src, int lane, int4 m, float2& sum)
{
    __half2 xa = __ldg((const __half2*)(src + (size_t)m.x * DIM) + lane);
    __half2 xb = __ldg((const __half2*)(src + (size_t)m.z * DIM) + lane);
    float va = __int_as_float(m.y);
    float vb = __int_as_float(m.w);
    float2 fa = __half22float2(xa);
    float2 fb = __half22float2(xb);
    sum.x = fmaf(fa.x, va, sum.x); sum.y = fmaf(fa.y, va, sum.y);
    sum.x = fmaf(fb.x, vb, sum.x); sum.y = fmaf(fb.y, vb, sum.y);
}

__device__ __forceinline__ float2 row_segsum(
    const __half* __restrict__ src, int row, int lane)
{
    int cnt = __ldg(&g_cnt[row]);
    if (cnt > CAP) cnt = CAP;
    const int2* ep = g_bucket + (size_t)row * CAP;

    float2 sum = make_float2(0.f, 0.f);
    int i = 0;
    for (; i + 7 < cnt; i += 8) {                    // 8-edge unroll
        int4 m0 = __ldg((const int4*)(ep + i));
        int4 m1 = __ldg((const int4*)(ep + i + 2));
        int4 m2 = __ldg((const int4*)(ep + i + 4));
        int4 m3 = __ldg((const int4*)(ep + i + 6));
        edge2_fma(src, lane, m0, sum);
        edge2_fma(src, lane, m1, sum);
        edge2_fma(src, lane, m2, sum);
        edge2_fma(src, lane, m3, sum);
    }
    for (; i + 1 < cnt; i += 2) {                    // 2-edge step
        int4 m = __ldg((const int4*)(ep + i));
        edge2_fma(src, lane, m, sum);
    }
    if (i < cnt) {                                   // odd tail
        int2 ev = __ldg(ep + i);
        float v = __int_as_float(ev.y);
        __half2 x = __ldg((const __half2*)(src + (size_t)ev.x * DIM) + lane);
        float2 f = __half22float2(x);
        sum.x = fmaf(f.x, v, sum.x);
        sum.y = fmaf(f.y, v, sum.y);
    }
    return sum;
}

__global__ __launch_bounds__(256) void spmm_kernel(
    const __half* __restrict__ src,
    __half*       __restrict__ dst)
{
    int warp = (blockIdx.x * blockDim.x + threadIdx.x) >> 5;
    int lane = threadIdx.x & 31;
    if (warp >= N_NODES) return;
    float2 sum = row_segsum(src, warp, lane);
    ((__half2*)dst)[(size_t)warp * (DIM / 2) + lane] =
        __floats2half2_rn(sum.x, sum.y);
}

// Layer 3 + final combine: out = (e0_f32 + e1 + e2 + sum3) * 0.25
__global__ __launch_bounds__(256) void spmm_final_kernel(
    const __half* __restrict__ src,        // h2 (e2): gather source
    const float*  __restrict__ user_emb,
    const float*  __restrict__ item_emb,
    float*        __restrict__ out)
{
    int warp = (blockIdx.x * blockDim.x + threadIdx.x) >> 5;
    int lane = threadIdx.x & 31;
    if (warp >= N_NODES) return;
    float2 sum = row_segsum(src, warp, lane);

    size_t o = (size_t)warp * (DIM / 2) + lane;
    float2 e1 = __half22float2(__ldg((const __half2*)g_h1 + o));
    float2 e2 = __half22float2(__ldg((const __half2*)g_h2 + o));
    const float* inp = (warp < N_USERS)
        ? user_emb + (size_t)warp * DIM
        : item_emb + (size_t)(warp - N_USERS) * DIM;
    float2 e0 = __ldg((const float2*)inp + lane);

    float2 r;
    r.x = (e0.x + e1.x + e2.x + sum.x) * 0.25f;
    r.y = (e0.y + e1.y + e2.y + sum.y) * 0.25f;
    ((float2*)out)[o] = r;
}

extern "C" void kernel_launch(void* const* d_in, const int* in_sizes, int n_in,
                              void* d_out, int out_size)
{
    const int*   rows     = (const int*)  d_in[0];
    const int*   cols     = (const int*)  d_in[1];
    const float* vals     = (const float*)d_in[2];
    const float* user_emb = (const float*)d_in[3];
    const float* item_emb = (const float*)d_in[4];
    float*       out      = (float*)d_out;

    __half *h0, *h1, *h2;
    cudaGetSymbolAddress((void**)&h0, g_h0);
    cudaGetSymbolAddress((void**)&h1, g_h1);
    cudaGetSymbolAddress((void**)&h2, g_h2);

    const int thr = 256;
    const int bucket_blocks = (NNZ / 4 + thr - 1) / thr;
    const int vec_blocks  = (int)((TOTAL4 + thr - 1) / thr);
    const int spmm_blocks = (int)(((long long)N_NODES * 32 + thr - 1) / thr);

    init_kernel<<<vec_blocks, thr>>>(user_emb, item_emb);
    bucket_kernel<<<bucket_blocks, thr>>>(rows, cols, vals);

    spmm_kernel<<<spmm_blocks, thr>>>(h0, h1);              // e1 = A e0
    spmm_kernel<<<spmm_blocks, thr>>>(h1, h2);              // e2 = A e1
    spmm_final_kernel<<<spmm_blocks, thr>>>(h2, user_emb, item_emb, out);
}

// round 12
// speedup vs baseline: 1.2478x; 1.1446x over previous
#include <cuda_runtime.h>
#include <cuda_fp16.h>

#define N_USERS 100000
#define N_ITEMS 200000
#define N_NODES (N_USERS + N_ITEMS)
#define NNZ     9600000
#define DIM     64
#define TOTAL   ((size_t)N_NODES * DIM)
#define TOTAL4  (TOTAL / 4)
#define CAP     128                     // slots/row; mean degree 32, ~17 sigma
#define WARPS_PER_BLOCK 8

// Scratch (__device__ globals, alloc-free rule).
// h0 = fp16(e0), h1 = e1, h2 = e2. Final combine reads fp32 inputs directly.
__device__ __align__(16) __half g_h0[TOTAL];
__device__ __align__(16) __half g_h1[TOTAL];
__device__ __align__(16) __half g_h2[TOTAL];
__device__ __align__(16) int2   g_bucket[(size_t)N_NODES * CAP];
__device__ int g_cnt[N_NODES];

// ---------------------------------------------------------------------------
// init: g_h0 = fp16(concat(user,item)); g_cnt = 0.
// ---------------------------------------------------------------------------
__global__ __launch_bounds__(256) void init_kernel(
    const float* __restrict__ user_emb,
    const float* __restrict__ item_emb)
{
    size_t i = (size_t)blockIdx.x * blockDim.x + threadIdx.x;
    if (i < N_NODES) g_cnt[i] = 0;
    if (i >= TOTAL4) return;
    const size_t ub = (size_t)N_USERS * DIM / 4;
    float4 v = (i < ub) ? ((const float4*)user_emb)[i]
                        : ((const float4*)item_emb)[i - ub];
    uint2 h;
    __half2 h01 = __floats2half2_rn(v.x, v.y);
    __half2 h23 = __floats2half2_rn(v.z, v.w);
    h.x = *(unsigned*)&h01;
    h.y = *(unsigned*)&h23;
    ((uint2*)g_h0)[i] = h;
}

// ---------------------------------------------------------------------------
// Single-pass bucketing, 4 edges/thread via int4 loads (NNZ % 4 == 0).
// ---------------------------------------------------------------------------
__global__ __launch_bounds__(256) void bucket_kernel(
    const int*   __restrict__ rows,
    const int*   __restrict__ cols,
    const float* __restrict__ vals)
{
    int t = blockIdx.x * blockDim.x + threadIdx.x;
    int e = t * 4;
    if (e >= NNZ) return;
    int4 r4 = __ldcs((const int4*)(rows + e));
    int4 c4 = __ldcs((const int4*)(cols + e));
    int4 v4 = __ldcs((const int4*)(vals + e));
    int rr[4] = {r4.x, r4.y, r4.z, r4.w};
    int cc[4] = {c4.x, c4.y, c4.z, c4.w};
    int vv[4] = {v4.x, v4.y, v4.z, v4.w};
    #pragma unroll
    for (int k = 0; k < 4; k++) {
        int pos = atomicAdd(&g_cnt[rr[k]], 1);
        if (pos < CAP)
            g_bucket[(size_t)rr[k] * CAP + pos] = make_int2(cc[k], vv[k]);
    }
}

// ---------------------------------------------------------------------------
// Warp-per-row segment sum with smem meta staging: one coalesced lane-parallel
// LDG pass copies the row's edge list into shared memory, then the mainloop
// reads meta via broadcast LDS.128 (29 cyc) instead of L2 LDG (~250 cyc),
// cutting the per-iteration dependence chain roughly in half.
// ---------------------------------------------------------------------------
__device__ __forceinline__ void edge2_fma(
    const __half* __restrict__ src, int lane, int4 m, float2& sum)
{
    __half2 xa = __ldg((const __half2*)(src + (size_t)m.x * DIM) + lane);
    __half2 xb = __ldg((const __half2*)(src + (size_t)m.z * DIM) + lane);
    float va = __int_as_float(m.y);
    float vb = __int_as_float(m.w);
    float2 fa = __half22float2(xa);
    float2 fb = __half22float2(xb);
    sum.x = fmaf(fa.x, va, sum.x); sum.y = fmaf(fa.y, va, sum.y);
    sum.x = fmaf(fb.x, vb, sum.x); sum.y = fmaf(fb.y, vb, sum.y);
}

__device__ __forceinline__ float2 row_segsum(
    const __half* __restrict__ src, int2* __restrict__ sm, int row, int lane)
{
    int cnt = __ldg(&g_cnt[row]);
    if (cnt > CAP) cnt = CAP;
    const int2* ep = g_bucket + (size_t)row * CAP;

    // Stage meta into smem: coalesced, lane-parallel (1 pass for cnt <= 32).
    for (int b = lane; b < cnt; b += 32)
        sm[b] = __ldg(ep + b);
    __syncwarp();

    float2 sum = make_float2(0.f, 0.f);
    int i = 0;
    for (; i + 7 < cnt; i += 8) {                    // 8-edge unroll, LDS meta
        int4 m0 = *(const int4*)(sm + i);
        int4 m1 = *(const int4*)(sm + i + 2);
        int4 m2 = *(const int4*)(sm + i + 4);
        int4 m3 = *(const int4*)(sm + i + 6);
        edge2_fma(src, lane, m0, sum);
        edge2_fma(src, lane, m1, sum);
        edge2_fma(src, lane, m2, sum);
        edge2_fma(src, lane, m3, sum);
    }
    for (; i + 1 < cnt; i += 2) {                    // 2-edge step (i even)
        int4 m = *(const int4*)(sm + i);
        edge2_fma(src, lane, m, sum);
    }
    if (i < cnt) {                                   // odd tail
        int2 ev = sm[i];
        float v = __int_as_float(ev.y);
        __half2 x = __ldg((const __half2*)(src + (size_t)ev.x * DIM) + lane);
        float2 f = __half22float2(x);
        sum.x = fmaf(f.x, v, sum.x);
        sum.y = fmaf(f.y, v, sum.y);
    }
    __syncwarp();                                    // protect smem reuse
    return sum;
}

__global__ __launch_bounds__(256) void spmm_kernel(
    const __half* __restrict__ src,
    __half*       __restrict__ dst)
{
    __shared__ __align__(16) int2 s_meta[WARPS_PER_BLOCK][CAP];
    int warp = (blockIdx.x * blockDim.x + threadIdx.x) >> 5;
    int lane = threadIdx.x & 31;
    if (warp >= N_NODES) return;
    float2 sum = row_segsum(src, s_meta[(threadIdx.x >> 5)], warp, lane);
    ((__half2*)dst)[(size_t)warp * (DIM / 2) + lane] =
        __floats2half2_rn(sum.x, sum.y);
}

// Layer 3 + final combine: out = (e0_f32 + e1 + e2 + sum3) * 0.25
__global__ __launch_bounds__(256) void spmm_final_kernel(
    const __half* __restrict__ src,        // h2 (e2): gather source
    const float*  __restrict__ user_emb,
    const float*  __restrict__ item_emb,
    float*        __restrict__ out)
{
    __shared__ __align__(16) int2 s_meta[WARPS_PER_BLOCK][CAP];
    int warp = (blockIdx.x * blockDim.x + threadIdx.x) >> 5;
    int lane = threadIdx.x & 31;
    if (warp >= N_NODES) return;
    float2 sum = row_segsum(src, s_meta[(threadIdx.x >> 5)], warp, lane);

    size_t o = (size_t)warp * (DIM / 2) + lane;
    float2 e1 = __half22float2(__ldg((const __half2*)g_h1 + o));
    float2 e2 = __half22float2(__ldg((const __half2*)g_h2 + o));
    const float* inp = (warp < N_USERS)
        ? user_emb + (size_t)warp * DIM
        : item_emb + (size_t)(warp - N_USERS) * DIM;
    float2 e0 = __ldg((const float2*)inp + lane);

    float2 r;
    r.x = (e0.x + e1.x + e2.x + sum.x) * 0.25f;
    r.y = (e0.y + e1.y + e2.y + sum.y) * 0.25f;
    ((float2*)out)[o] = r;
}

extern "C" void kernel_launch(void* const* d_in, const int* in_sizes, int n_in,
                              void* d_out, int out_size)
{
    const int*   rows     = (const int*)  d_in[0];
    const int*   cols     = (const int*)  d_in[1];
    const float* vals     = (const float*)d_in[2];
    const float* user_emb = (const float*)d_in[3];
    const float* item_emb = (const float*)d_in[4];
    float*       out      = (float*)d_out;

    __half *h0, *h1, *h2;
    cudaGetSymbolAddress((void**)&h0, g_h0);
    cudaGetSymbolAddress((void**)&h1, g_h1);
    cudaGetSymbolAddress((void**)&h2, g_h2);

    const int thr = 256;
    const int bucket_blocks = (NNZ / 4 + thr - 1) / thr;
    const int vec_blocks  = (int)((TOTAL4 + thr - 1) / thr);
    const int spmm_blocks = (int)(((long long)N_NODES * 32 + thr - 1) / thr);

    init_kernel<<<vec_blocks, thr>>>(user_emb, item_emb);
    bucket_kernel<<<bucket_blocks, thr>>>(rows, cols, vals);

    spmm_kernel<<<spmm_blocks, thr>>>(h0, h1);              // e1 = A e0
    spmm_kernel<<<spmm_blocks, thr>>>(h1, h2);              // e2 = A e1
    spmm_final_kernel<<<spmm_blocks, thr>>>(h2, user_emb, item_emb, out);
}